// round 15
// baseline (speedup 1.0000x reference)
#include <cuda_runtime.h>
#include <cuda_fp16.h>
#include <cstdint>
#include <math.h>

#define B_WIN 2048
#define N_TOK 64
#define DIMC  512
#define NH    16
#define HD    32
#define PP    16
#define MQ    (B_WIN * N_TOK)   // 131072
#define MP    (B_WIN * PP)      // 32768

// ---------------- scratch (allocation-free rule: __device__ globals) --------
__device__ __half g_x16[(size_t)MQ * DIMC];
__device__ __half g_XK [(size_t)MP * DIMC];
__device__ __half g_XV [(size_t)MP * DIMC];
__device__ __half g_KP16[(size_t)MP * DIMC];
__device__ __half g_VP16[(size_t)MP * DIMC];
__device__ __half g_O16[(size_t)MQ * DIMC];
__device__ __half g_WT [4 * DIMC * DIMC];     // transposed weights [N,K] K-major fp16
__device__ float  g_sk[PP];
__device__ float  g_sv[PP];

// ======================= PTX helpers =======================================
__device__ __forceinline__ uint32_t smem_u32(const void* p) {
    uint32_t a;
    asm("{ .reg .u64 t; cvta.to.shared.u64 t, %1; cvt.u32.u64 %0, t; }" : "=r"(a) : "l"(p));
    return a;
}
__device__ __forceinline__ void cp16(uint32_t saddr, const void* g) {
    asm volatile("cp.async.cg.shared.global [%0], [%1], 16;" :: "r"(saddr), "l"(g));
}
__device__ __forceinline__ void cp_commit() { asm volatile("cp.async.commit_group;"); }
__device__ __forceinline__ void cp_wait1()  { asm volatile("cp.async.wait_group 1;"); }
__device__ __forceinline__ void cp_wait0()  { asm volatile("cp.async.wait_group 0;"); }
__device__ __forceinline__ void ldsm_x4(uint32_t* r, uint32_t addr) {
    asm volatile("ldmatrix.sync.aligned.m8n8.x4.shared.b16 {%0,%1,%2,%3}, [%4];"
        : "=r"(r[0]), "=r"(r[1]), "=r"(r[2]), "=r"(r[3]) : "r"(addr));
}
__device__ __forceinline__ void mma16816(float* c, const uint32_t* a, const uint32_t* b) {
    asm volatile("mma.sync.aligned.m16n8k16.row.col.f32.f16.f16.f32 "
        "{%0,%1,%2,%3}, {%4,%5,%6,%7}, {%8,%9}, {%0,%1,%2,%3};"
        : "+f"(c[0]), "+f"(c[1]), "+f"(c[2]), "+f"(c[3])
        : "r"(a[0]), "r"(a[1]), "r"(a[2]), "r"(a[3]), "r"(b[0]), "r"(b[1]));
}

// ---------------- weight transpose -> fp16 [N,K] ---------------------------
__global__ void transpose_kernel(const float* __restrict__ w_qkv,
                                 const float* __restrict__ w_proj) {
    __shared__ float t[32][33];
    int m = blockIdx.z;
    const float* src = (m < 3) ? w_qkv : w_proj;
    int ld = (m < 3) ? 3 * DIMC : DIMC;
    int coloff = (m < 3) ? m * DIMC : 0;
    int bx = blockIdx.x * 32, by = blockIdx.y * 32;
    int tx = threadIdx.x, ty = threadIdx.y;
#pragma unroll
    for (int i = 0; i < 32; i += 8)
        t[ty + i][tx] = src[(size_t)(by + ty + i) * ld + coloff + bx + tx];
    __syncthreads();
    __half* dst = g_WT + (size_t)m * DIMC * DIMC;
#pragma unroll
    for (int i = 0; i < 32; i += 8)
        dst[(size_t)(bx + ty + i) * DIMC + by + tx] = __float2half_rn(t[tx][ty + i]);
}

// ---------------- row sums of w_k / w_v ------------------------------------
__global__ void rowsum_kernel(const float* __restrict__ w_k,
                              const float* __restrict__ w_v) {
    int p = threadIdx.x;
    if (p < PP) {
        float s1 = 0.f, s2 = 0.f;
        for (int n = 0; n < N_TOK; n++) { s1 += w_k[p * N_TOK + n]; s2 += w_v[p * N_TOK + n]; }
        g_sk[p] = s1;
        g_sv[p] = s2;
    }
}

// ====== fused xproj: reads x fp32 once, emits x16 + XK + XV (all fp16) =====
#define XP_STAGE_F (16 * DIMC)
#define XP_SMEM    (2 * XP_STAGE_F * 4 + 64 * PP * 8)

__global__ __launch_bounds__(256, 2) void xproj_kernel(
    const float* __restrict__ x,
    const float* __restrict__ w_k, const float* __restrict__ w_v) {
    extern __shared__ __align__(16) char xsm[];
    float*  xs  = (float*)xsm;
    float2* swp = (float2*)(xsm + 2 * XP_STAGE_F * 4);
    uint32_t sbase = smem_u32(xsm);

    int b = blockIdx.x;
    int t = threadIdx.x;
    const float* xg = x + (size_t)b * N_TOK * DIMC;

    for (int i = t; i < N_TOK * PP; i += 256) {
        int p = i & 15, n = i >> 4;
        swp[n * PP + p] = make_float2(w_k[p * N_TOK + n], w_v[p * N_TOK + n]);
    }

    auto load_stage = [&](int s) {
        uint32_t dst = sbase + (s & 1) * (XP_STAGE_F * 4);
        const float* src = xg + (size_t)s * XP_STAGE_F;
#pragma unroll
        for (int i = 0; i < 8; i++)
            cp16(dst + t * 16 + i * 4096, src + t * 4 + i * 1024);
    };

    float2 ak[PP], av[PP];
#pragma unroll
    for (int p = 0; p < PP; p++) { ak[p] = make_float2(0.f, 0.f); av[p] = make_float2(0.f, 0.f); }

    load_stage(0); cp_commit();

    for (int s = 0; s < 4; s++) {
        if (s < 3) { load_stage(s + 1); cp_commit(); cp_wait1(); }
        else cp_wait0();
        __syncthreads();
        const float* buf = xs + (s & 1) * XP_STAGE_F;
#pragma unroll 4
        for (int nl = 0; nl < 16; nl++) {
            int n = s * 16 + nl;
            float2 xv = *(const float2*)(buf + nl * DIMC + 2 * t);
            *(__half2*)(g_x16 + ((size_t)b * N_TOK + n) * DIMC + 2 * t) =
                __floats2half2_rn(xv.x, xv.y);
            const float2* wrow = swp + n * PP;
#pragma unroll
            for (int p = 0; p < PP; p++) {
                float2 w = wrow[p];
                ak[p].x += w.x * xv.x; ak[p].y += w.x * xv.y;
                av[p].x += w.y * xv.x; av[p].y += w.y * xv.y;
            }
        }
        __syncthreads();
    }

#pragma unroll
    for (int p = 0; p < PP; p++) {
        size_t row = (size_t)b * PP + p;
        *(__half2*)(g_XK + row * DIMC + 2 * t) = __floats2half2_rn(ak[p].x, ak[p].y);
        *(__half2*)(g_XV + row * DIMC + 2 * t) = __floats2half2_rn(av[p].x, av[p].y);
    }
}

// =========== shared mainloop: Round-9 body, ONE barrier per K-iter =========
// Safety of the removed trailing barrier: load_stage(kc+2) at iteration kc
// overwrites stage (kc-1)%3, whose compute (iteration kc-1) is ordered before
// this iteration's TOP barrier for every warp. Unconditional cp_commit keeps
// the wait_group 1 accounting aligned on the tail (empty groups).
#define STAGEB 20480
#define DYN_SMEM (3 * STAGEB)

__device__ __forceinline__ void gemm_mainloop(
    const __half* __restrict__ Ag, const __half* __restrict__ Bg,
    uint32_t sb, float acc[2][8][4]) {
    int tid = threadIdx.x;
    int wid = tid >> 5, lane = tid & 31;

    int grow = tid >> 2, gcol = tid & 3;
    auto load_stage = [&](int kc, int st) {
        uint32_t a0 = sb + st * STAGEB;
        uint32_t b0 = a0 + 10240;
        const __half* Agk = Ag + kc * 32;
        const __half* Bgk = Bg + kc * 32;
#pragma unroll
        for (int i = 0; i < 2; i++) {
            int row = grow + i * 64;
            cp16(a0 + row * 80 + gcol * 16, Agk + (size_t)row * DIMC + gcol * 8);
            cp16(b0 + row * 80 + gcol * 16, Bgk + (size_t)row * DIMC + gcol * 8);
        }
    };

#pragma unroll
    for (int mt = 0; mt < 2; mt++)
#pragma unroll
        for (int nt = 0; nt < 8; nt++)
#pragma unroll
            for (int e = 0; e < 4; e++) acc[mt][nt][e] = 0.f;

    int warp_m = wid & 3, warp_n = wid >> 2;
    int arow = (lane & 7) + ((lane >> 3) & 1) * 8;
    int achk = lane >> 4;
    int brow = (lane & 7) + ((lane >> 4) & 1) * 8;
    int bchk = (lane >> 3) & 1;

    load_stage(0, 0); cp_commit();
    load_stage(1, 1); cp_commit();

    const int NK = 16;
#pragma unroll 3
    for (int kc = 0; kc < NK; kc++) {
        int st = kc % 3;
        cp_wait1();
        __syncthreads();
        if (kc + 2 < NK) load_stage(kc + 2, (kc + 2) % 3);
        cp_commit();   // unconditional: empty tail groups keep wait1 accounting

        uint32_t aS = sb + st * STAGEB;
        uint32_t bS = aS + 10240;
#pragma unroll
        for (int ks = 0; ks < 2; ks++) {
            uint32_t af[2][4];
            uint32_t abase = aS + (uint32_t)((warp_m * 32 + arow) * 80 + ks * 32 + achk * 16);
            ldsm_x4(af[0], abase);
            ldsm_x4(af[1], abase + 16 * 80);
            uint32_t bf[8][2];
#pragma unroll
            for (int bt = 0; bt < 4; bt++) {
                uint32_t t4[4];
                ldsm_x4(t4, bS + (uint32_t)((warp_n * 64 + bt * 16 + brow) * 80 + ks * 32 + bchk * 16));
                bf[2 * bt][0] = t4[0]; bf[2 * bt][1] = t4[1];
                bf[2 * bt + 1][0] = t4[2]; bf[2 * bt + 1][1] = t4[3];
            }
#pragma unroll
            for (int mt = 0; mt < 2; mt++)
#pragma unroll
                for (int nt = 0; nt < 8; nt++)
                    mma16816(acc[mt][nt], af[mt], bf[nt]);
        }
        // no trailing barrier (see header comment)
    }
    __syncthreads();   // callers may reuse pipeline smem after return
}

// =================== plain GEMM kernels (out-proj, KV) =====================
template <typename OutT>
__device__ __forceinline__ void gemm_epilogue(
    OutT* __restrict__ C, int bm, int bn, float acc[2][8][4],
    const float* __restrict__ biascol, const float* __restrict__ srow, float alpha) {
    int tid = threadIdx.x;
    int wid = tid >> 5, lane = tid & 31;
    int warp_m = wid & 3, warp_n = wid >> 2;
    int rbase = bm * 128 + warp_m * 32 + (lane >> 2);
    int cbase = bn * 128 + warp_n * 64 + (lane & 3) * 2;
#pragma unroll
    for (int mt = 0; mt < 2; mt++) {
#pragma unroll
        for (int h = 0; h < 2; h++) {
            int r = rbase + mt * 16 + h * 8;
            float sr = srow ? srow[r & 15] : 1.f;
            OutT* crow = C + (size_t)r * DIMC;
#pragma unroll
            for (int nt = 0; nt < 8; nt++) {
                int c = cbase + nt * 8;
                float ox = (acc[mt][nt][h * 2 + 0] + sr * biascol[c]) * alpha;
                float oy = (acc[mt][nt][h * 2 + 1] + sr * biascol[c + 1]) * alpha;
                if constexpr (sizeof(OutT) == 2) {
                    *(__half2*)(crow + c) = __floats2half2_rn(ox, oy);
                } else {
                    *(float2*)(crow + c) = make_float2(ox, oy);
                }
            }
        }
    }
}

template <typename OutT>
__global__ __launch_bounds__(256, 2) void tgemm_kernel(
    const __half* __restrict__ A, const __half* __restrict__ Bt,
    OutT* __restrict__ C,
    const float* __restrict__ biascol, const float* __restrict__ srow, float alpha) {
    extern __shared__ __align__(16) char smem[];
    float acc[2][8][4];
    gemm_mainloop(A + (size_t)blockIdx.y * 128 * DIMC,
                  Bt + (size_t)blockIdx.x * 128 * DIMC, smem_u32(smem), acc);
    gemm_epilogue<OutT>(C, blockIdx.y, blockIdx.x, acc, biascol, srow, alpha);
}

// fused KP/VP GEMM: blockIdx.y selects K half vs V half
__global__ __launch_bounds__(256, 2) void kvgemm_kernel(
    const float* __restrict__ b_qkv) {
    extern __shared__ __align__(16) char smem[];
    int by = blockIdx.y;
    int isV = (by >= MP / 128);
    int bm = isV ? by - MP / 128 : by;
    const __half* A  = isV ? g_XV : g_XK;
    const __half* Bt = g_WT + (size_t)(1 + isV) * DIMC * DIMC;
    __half* C        = isV ? g_VP16 : g_KP16;
    float acc[2][8][4];
    gemm_mainloop(A + (size_t)bm * 128 * DIMC,
                  Bt + (size_t)blockIdx.x * 128 * DIMC, smem_u32(smem), acc);
    gemm_epilogue<__half>(C, bm, blockIdx.x, acc,
                          b_qkv + (1 + isV) * DIMC, isV ? g_sv : g_sk, 1.f);
}

// ============ fused Q-GEMM + attention =====================================
#define QS_BYTES 67584                 // 128*132*4
#define QA_SMEM  (QS_BYTES + 2 * 8192)

__global__ __launch_bounds__(256, 2) void qattn_kernel(
    const float* __restrict__ b_qkv, const float* __restrict__ btab) {
    extern __shared__ __align__(16) char smem[];
    uint32_t sb = smem_u32(smem);
    float*  qs  = (float*)smem;
    __half* kps = (__half*)(smem + QS_BYTES);
    __half* vps = (__half*)(smem + QS_BYTES + 8192);
    uint32_t kv_s = sb + QS_BYTES;

    int tid = threadIdx.x;
    int wid = tid >> 5, lane = tid & 31;
    int bn = blockIdx.x, bm = blockIdx.y;

    // prologue cp.async group: this CTA's KP/VP slices (drained by first wait1)
#pragma unroll
    for (int i = 0; i < 2; i++) {
        int c = tid + i * 256;
        int row = c >> 4, off = c & 15;
        size_t gofs = (size_t)(bm * 32 + row) * DIMC + bn * 128 + off * 8;
        cp16(kv_s + row * 256 + off * 16, g_KP16 + gofs);
        cp16(kv_s + 8192 + row * 256 + off * 16, g_VP16 + gofs);
    }
    cp_commit();

    float acc[2][8][4];
    gemm_mainloop(g_x16 + (size_t)bm * 128 * DIMC,
                  g_WT + (size_t)bn * 128 * DIMC, sb, acc);
    // mainloop ends with one barrier: stages dead, safe to overwrite with q_s

    const float scale = 0.17677669529663687f;
    {
        int warp_m = wid & 3, warp_n = wid >> 2;
        int rl = warp_m * 32 + (lane >> 2);
        int clb = warp_n * 64 + (lane & 3) * 2;
#pragma unroll
        for (int mt = 0; mt < 2; mt++)
#pragma unroll
            for (int h = 0; h < 2; h++) {
                int r = rl + mt * 16 + h * 8;
#pragma unroll
                for (int nt = 0; nt < 8; nt++) {
                    int c = clb + nt * 8;
                    float bx = b_qkv[bn * 128 + c];
                    float by = b_qkv[bn * 128 + c + 1];
                    qs[(c) * 132 + r]     = (acc[mt][nt][h * 2 + 0] + bx) * scale;
                    qs[(c + 1) * 132 + r] = (acc[mt][nt][h * 2 + 1] + by) * scale;
                }
            }
    }
    __syncthreads();

    // attention: 512 tasks (wb, hl, n) over 256 threads
#pragma unroll
    for (int it = 0; it < 2; it++) {
        int task = tid + it * 256;
        int wb = task >> 8, rem = task & 255;
        int hl = rem >> 6, n = rem & 63;
        int row = wb * 64 + n;
        int h = bn * 4 + hl;

        float q[HD];
#pragma unroll
        for (int d = 0; d < HD; d++) q[d] = qs[(hl * 32 + d) * 132 + row];

        int yn = n >> 3, xn = n & 7;
        float logit[PP];
#pragma unroll
        for (int p = 0; p < PP; p++) {
            const __half2* kr = (const __half2*)(kps + (wb * 16 + p) * 128 + hl * 32);
            float s = 0.f;
#pragma unroll
            for (int d2 = 0; d2 < 16; d2++) {
                float2 f = __half22float2(kr[d2]);
                s += q[2 * d2] * f.x + q[2 * d2 + 1] * f.y;
            }
            int yp = p >> 3, xp = p & 7;
            int idx = (yn - yp + 7) * 15 + (xn - xp + 7);
            logit[p] = s + btab[idx * NH + h];
        }
        float m = logit[0];
#pragma unroll
        for (int p = 1; p < PP; p++) m = fmaxf(m, logit[p]);
        float sum = 0.f;
#pragma unroll
        for (int p = 0; p < PP; p++) {
            float e = __expf(logit[p] - m);
            logit[p] = e;
            sum += e;
        }
        float inv = 1.f / sum;
        float o[HD];
#pragma unroll
        for (int d = 0; d < HD; d++) o[d] = 0.f;
#pragma unroll
        for (int p = 0; p < PP; p++) {
            float w = logit[p] * inv;
            const __half2* vr = (const __half2*)(vps + (wb * 16 + p) * 128 + hl * 32);
#pragma unroll
            for (int d2 = 0; d2 < 16; d2++) {
                float2 f = __half22float2(vr[d2]);
                o[2 * d2] += w * f.x;
                o[2 * d2 + 1] += w * f.y;
            }
        }
        __half2* orow = (__half2*)(g_O16 + ((size_t)(bm * 128 + row)) * DIMC + bn * 128 + hl * 32);
#pragma unroll
        for (int d2 = 0; d2 < 16; d2++)
            orow[d2] = __floats2half2_rn(o[2 * d2], o[2 * d2 + 1]);
    }
}

// ---------------------------------------------------------------------------
extern "C" void kernel_launch(void* const* d_in, const int* in_sizes, int n_in,
                              void* d_out, int out_size) {
    const float* x      = (const float*)d_in[0];
    const float* w_qkv  = (const float*)d_in[1];
    const float* b_qkv  = (const float*)d_in[2];
    const float* w_proj = (const float*)d_in[3];
    const float* b_proj = (const float*)d_in[4];
    const float* w_k    = (const float*)d_in[5];
    const float* w_v    = (const float*)d_in[6];
    const float* btab   = (const float*)d_in[7];
    float* out = (float*)d_out;

    __half *O16, *WT;
    cudaGetSymbolAddress((void**)&O16, g_O16);
    cudaGetSymbolAddress((void**)&WT,  g_WT);

    cudaFuncSetAttribute(tgemm_kernel<float>, cudaFuncAttributeMaxDynamicSharedMemorySize, DYN_SMEM);
    cudaFuncSetAttribute(kvgemm_kernel, cudaFuncAttributeMaxDynamicSharedMemorySize, DYN_SMEM);
    cudaFuncSetAttribute(qattn_kernel, cudaFuncAttributeMaxDynamicSharedMemorySize, QA_SMEM);
    cudaFuncSetAttribute(xproj_kernel, cudaFuncAttributeMaxDynamicSharedMemorySize, XP_SMEM);

    transpose_kernel<<<dim3(16, 16, 4), dim3(32, 8)>>>(w_qkv, w_proj);
    rowsum_kernel<<<1, 32>>>(w_k, w_v);
    xproj_kernel<<<B_WIN, 256, XP_SMEM>>>(x, w_k, w_v);

    // KP16 / VP16 in one launch
    kvgemm_kernel<<<dim3(4, 2 * MP / 128), 256, DYN_SMEM>>>(b_qkv);

    // fused Q-GEMM + attention -> O16
    qattn_kernel<<<dim3(4, MQ / 128), 256, QA_SMEM>>>(b_qkv, btab);

    // out = O @ w_proj + b_proj   (fp32 out)
    tgemm_kernel<float><<<dim3(4, MQ / 128), 256, DYN_SMEM>>>(
        O16, WT + 3 * DIMC * DIMC, out, b_proj, nullptr, 1.f);
}

// round 16
// speedup vs baseline: 1.1101x; 1.1101x over previous
#include <cuda_runtime.h>
#include <cuda_fp16.h>
#include <cstdint>
#include <math.h>

#define B_WIN 2048
#define N_TOK 64
#define DIMC  512
#define NH    16
#define HD    32
#define PP    16
#define MQ    (B_WIN * N_TOK)   // 131072
#define MP    (B_WIN * PP)      // 32768

// ---------------- scratch (allocation-free rule: __device__ globals) --------
__device__ __half g_x16[(size_t)MQ * DIMC];
__device__ __half g_XK [(size_t)MP * DIMC];
__device__ __half g_XV [(size_t)MP * DIMC];
__device__ __half g_KP16[(size_t)MP * DIMC];
__device__ __half g_VP16[(size_t)MP * DIMC];
__device__ __half g_O16[(size_t)MQ * DIMC];
__device__ __half g_WT [4 * DIMC * DIMC];     // transposed weights [N,K] K-major fp16
__device__ float  g_sk[PP];
__device__ float  g_sv[PP];

// ======================= PTX helpers =======================================
__device__ __forceinline__ uint32_t smem_u32(const void* p) {
    uint32_t a;
    asm("{ .reg .u64 t; cvta.to.shared.u64 t, %1; cvt.u32.u64 %0, t; }" : "=r"(a) : "l"(p));
    return a;
}
__device__ __forceinline__ void cp16(uint32_t saddr, const void* g) {
    asm volatile("cp.async.cg.shared.global [%0], [%1], 16;" :: "r"(saddr), "l"(g));
}
__device__ __forceinline__ void cp_commit() { asm volatile("cp.async.commit_group;"); }
__device__ __forceinline__ void cp_wait1()  { asm volatile("cp.async.wait_group 1;"); }
__device__ __forceinline__ void cp_wait0()  { asm volatile("cp.async.wait_group 0;"); }
__device__ __forceinline__ void ldsm_x4(uint32_t* r, uint32_t addr) {
    asm volatile("ldmatrix.sync.aligned.m8n8.x4.shared.b16 {%0,%1,%2,%3}, [%4];"
        : "=r"(r[0]), "=r"(r[1]), "=r"(r[2]), "=r"(r[3]) : "r"(addr));
}
__device__ __forceinline__ void mma16816(float* c, const uint32_t* a, const uint32_t* b) {
    asm volatile("mma.sync.aligned.m16n8k16.row.col.f32.f16.f16.f32 "
        "{%0,%1,%2,%3}, {%4,%5,%6,%7}, {%8,%9}, {%0,%1,%2,%3};"
        : "+f"(c[0]), "+f"(c[1]), "+f"(c[2]), "+f"(c[3])
        : "r"(a[0]), "r"(a[1]), "r"(a[2]), "r"(a[3]), "r"(b[0]), "r"(b[1]));
}

// ---------------- weight transpose -> fp16 [N,K] ---------------------------
__global__ void transpose_kernel(const float* __restrict__ w_qkv,
                                 const float* __restrict__ w_proj) {
    __shared__ float t[32][33];
    int m = blockIdx.z;
    const float* src = (m < 3) ? w_qkv : w_proj;
    int ld = (m < 3) ? 3 * DIMC : DIMC;
    int coloff = (m < 3) ? m * DIMC : 0;
    int bx = blockIdx.x * 32, by = blockIdx.y * 32;
    int tx = threadIdx.x, ty = threadIdx.y;
#pragma unroll
    for (int i = 0; i < 32; i += 8)
        t[ty + i][tx] = src[(size_t)(by + ty + i) * ld + coloff + bx + tx];
    __syncthreads();
    __half* dst = g_WT + (size_t)m * DIMC * DIMC;
#pragma unroll
    for (int i = 0; i < 32; i += 8)
        dst[(size_t)(bx + ty + i) * DIMC + by + tx] = __float2half_rn(t[tx][ty + i]);
}

// ---------------- row sums of w_k / w_v ------------------------------------
__global__ void rowsum_kernel(const float* __restrict__ w_k,
                              const float* __restrict__ w_v) {
    int p = threadIdx.x;
    if (p < PP) {
        float s1 = 0.f, s2 = 0.f;
        for (int n = 0; n < N_TOK; n++) { s1 += w_k[p * N_TOK + n]; s2 += w_v[p * N_TOK + n]; }
        g_sk[p] = s1;
        g_sv[p] = s2;
    }
}

// ====== fused xproj: reads x fp32 once, emits x16 + XK + XV (all fp16) =====
#define XP_STAGE_F (16 * DIMC)
#define XP_SMEM    (2 * XP_STAGE_F * 4 + 64 * PP * 8)

__global__ __launch_bounds__(256, 2) void xproj_kernel(
    const float* __restrict__ x,
    const float* __restrict__ w_k, const float* __restrict__ w_v) {
    extern __shared__ __align__(16) char xsm[];
    float*  xs  = (float*)xsm;
    float2* swp = (float2*)(xsm + 2 * XP_STAGE_F * 4);
    uint32_t sbase = smem_u32(xsm);

    int b = blockIdx.x;
    int t = threadIdx.x;
    const float* xg = x + (size_t)b * N_TOK * DIMC;

    for (int i = t; i < N_TOK * PP; i += 256) {
        int p = i & 15, n = i >> 4;
        swp[n * PP + p] = make_float2(w_k[p * N_TOK + n], w_v[p * N_TOK + n]);
    }

    auto load_stage = [&](int s) {
        uint32_t dst = sbase + (s & 1) * (XP_STAGE_F * 4);
        const float* src = xg + (size_t)s * XP_STAGE_F;
#pragma unroll
        for (int i = 0; i < 8; i++)
            cp16(dst + t * 16 + i * 4096, src + t * 4 + i * 1024);
    };

    float2 ak[PP], av[PP];
#pragma unroll
    for (int p = 0; p < PP; p++) { ak[p] = make_float2(0.f, 0.f); av[p] = make_float2(0.f, 0.f); }

    load_stage(0); cp_commit();

    for (int s = 0; s < 4; s++) {
        if (s < 3) { load_stage(s + 1); cp_commit(); cp_wait1(); }
        else cp_wait0();
        __syncthreads();
        const float* buf = xs + (s & 1) * XP_STAGE_F;
#pragma unroll 4
        for (int nl = 0; nl < 16; nl++) {
            int n = s * 16 + nl;
            float2 xv = *(const float2*)(buf + nl * DIMC + 2 * t);
            *(__half2*)(g_x16 + ((size_t)b * N_TOK + n) * DIMC + 2 * t) =
                __floats2half2_rn(xv.x, xv.y);
            const float2* wrow = swp + n * PP;
#pragma unroll
            for (int p = 0; p < PP; p++) {
                float2 w = wrow[p];
                ak[p].x += w.x * xv.x; ak[p].y += w.x * xv.y;
                av[p].x += w.y * xv.x; av[p].y += w.y * xv.y;
            }
        }
        __syncthreads();
    }

#pragma unroll
    for (int p = 0; p < PP; p++) {
        size_t row = (size_t)b * PP + p;
        *(__half2*)(g_XK + row * DIMC + 2 * t) = __floats2half2_rn(ak[p].x, ak[p].y);
        *(__half2*)(g_XV + row * DIMC + 2 * t) = __floats2half2_rn(av[p].x, av[p].y);
    }
}

// =========== BK=32 mainloop (Round-9/14 proven body, UNCHANGED) ============
#define STAGEB 20480
#define DYN_SMEM (3 * STAGEB)

__device__ __forceinline__ void gemm_mainloop(
    const __half* __restrict__ Ag, const __half* __restrict__ Bg,
    uint32_t sb, float acc[2][8][4]) {
    int tid = threadIdx.x;
    int wid = tid >> 5, lane = tid & 31;

    int grow = tid >> 2, gcol = tid & 3;
    auto load_stage = [&](int kc, int st) {
        uint32_t a0 = sb + st * STAGEB;
        uint32_t b0 = a0 + 10240;
        const __half* Agk = Ag + kc * 32;
        const __half* Bgk = Bg + kc * 32;
#pragma unroll
        for (int i = 0; i < 2; i++) {
            int row = grow + i * 64;
            cp16(a0 + row * 80 + gcol * 16, Agk + (size_t)row * DIMC + gcol * 8);
            cp16(b0 + row * 80 + gcol * 16, Bgk + (size_t)row * DIMC + gcol * 8);
        }
    };

#pragma unroll
    for (int mt = 0; mt < 2; mt++)
#pragma unroll
        for (int nt = 0; nt < 8; nt++)
#pragma unroll
            for (int e = 0; e < 4; e++) acc[mt][nt][e] = 0.f;

    int warp_m = wid & 3, warp_n = wid >> 2;
    int arow = (lane & 7) + ((lane >> 3) & 1) * 8;
    int achk = lane >> 4;
    int brow = (lane & 7) + ((lane >> 4) & 1) * 8;
    int bchk = (lane >> 3) & 1;

    load_stage(0, 0); cp_commit();
    load_stage(1, 1); cp_commit();

    const int NK = 16;
    for (int kc = 0; kc < NK; kc++) {
        int st = kc % 3;
        cp_wait1();
        __syncthreads();
        if (kc + 2 < NK) load_stage(kc + 2, (kc + 2) % 3);
        cp_commit();

        uint32_t aS = sb + st * STAGEB;
        uint32_t bS = aS + 10240;
#pragma unroll
        for (int ks = 0; ks < 2; ks++) {
            uint32_t af[2][4];
            uint32_t abase = aS + (uint32_t)((warp_m * 32 + arow) * 80 + ks * 32 + achk * 16);
            ldsm_x4(af[0], abase);
            ldsm_x4(af[1], abase + 16 * 80);
            uint32_t bf[8][2];
#pragma unroll
            for (int bt = 0; bt < 4; bt++) {
                uint32_t t4[4];
                ldsm_x4(t4, bS + (uint32_t)((warp_n * 64 + bt * 16 + brow) * 80 + ks * 32 + bchk * 16));
                bf[2 * bt][0] = t4[0]; bf[2 * bt][1] = t4[1];
                bf[2 * bt + 1][0] = t4[2]; bf[2 * bt + 1][1] = t4[3];
            }
#pragma unroll
            for (int mt = 0; mt < 2; mt++)
#pragma unroll
                for (int nt = 0; nt < 8; nt++)
                    mma16816(acc[mt][nt], af[mt], bf[nt]);
        }
        __syncthreads();
    }
}

// =========== BK=64 mainloop: same lockstep pattern, half the barriers ======
// Pitch 144 B (72 halfs: 64 data + 8 pad). Bank math: row stride = 36 banks,
// ldsm's 8 rows hit banks {4r mod 32} — all distinct, conflict-free; same for
// the 16B cp.async stores (each 8-lane phase = one full 128B row).
#define STAGE64 36864              // (128 + 128) rows * 144 B
#define DYN_SMEM64 (3 * STAGE64)   // 110592 -> still 2 CTAs/SM

__device__ __forceinline__ void gemm_mainloop64(
    const __half* __restrict__ Ag, const __half* __restrict__ Bg,
    uint32_t sb, float acc[2][8][4]) {
    int tid = threadIdx.x;
    int wid = tid >> 5, lane = tid & 31;

    int grow = tid >> 3, gcol = tid & 7;   // 1024 16B-chunks per operand per stage
    auto load_stage = [&](int kc, int st) {
        uint32_t a0 = sb + st * STAGE64;
        uint32_t b0 = a0 + 18432;
        const __half* Agk = Ag + kc * 64;
        const __half* Bgk = Bg + kc * 64;
#pragma unroll
        for (int i = 0; i < 4; i++) {
            int row = grow + i * 32;
            cp16(a0 + row * 144 + gcol * 16, Agk + (size_t)row * DIMC + gcol * 8);
            cp16(b0 + row * 144 + gcol * 16, Bgk + (size_t)row * DIMC + gcol * 8);
        }
    };

#pragma unroll
    for (int mt = 0; mt < 2; mt++)
#pragma unroll
        for (int nt = 0; nt < 8; nt++)
#pragma unroll
            for (int e = 0; e < 4; e++) acc[mt][nt][e] = 0.f;

    int warp_m = wid & 3, warp_n = wid >> 2;
    int arow = (lane & 7) + ((lane >> 3) & 1) * 8;
    int achk = lane >> 4;
    int brow = (lane & 7) + ((lane >> 4) & 1) * 8;
    int bchk = (lane >> 3) & 1;

    load_stage(0, 0); cp_commit();
    load_stage(1, 1); cp_commit();

    const int NK = 8;
    for (int kc = 0; kc < NK; kc++) {
        int st = kc % 3;
        cp_wait1();
        __syncthreads();
        if (kc + 2 < NK) load_stage(kc + 2, (kc + 2) % 3);
        cp_commit();

        uint32_t aS = sb + st * STAGE64;
        uint32_t bS = aS + 18432;
#pragma unroll
        for (int ks = 0; ks < 4; ks++) {
            uint32_t af[2][4];
            uint32_t abase = aS + (uint32_t)((warp_m * 32 + arow) * 144 + ks * 32 + achk * 16);
            ldsm_x4(af[0], abase);
            ldsm_x4(af[1], abase + 16 * 144);
            uint32_t bf[8][2];
#pragma unroll
            for (int bt = 0; bt < 4; bt++) {
                uint32_t t4[4];
                ldsm_x4(t4, bS + (uint32_t)((warp_n * 64 + bt * 16 + brow) * 144 + ks * 32 + bchk * 16));
                bf[2 * bt][0] = t4[0]; bf[2 * bt][1] = t4[1];
                bf[2 * bt + 1][0] = t4[2]; bf[2 * bt + 1][1] = t4[3];
            }
#pragma unroll
            for (int mt = 0; mt < 2; mt++)
#pragma unroll
                for (int nt = 0; nt < 8; nt++)
                    mma16816(acc[mt][nt], af[mt], bf[nt]);
        }
        __syncthreads();
    }
}

// =================== plain GEMM kernels (out-proj, KV) =====================
template <typename OutT>
__device__ __forceinline__ void gemm_epilogue(
    OutT* __restrict__ C, int bm, int bn, float acc[2][8][4],
    const float* __restrict__ biascol, const float* __restrict__ srow, float alpha) {
    int tid = threadIdx.x;
    int wid = tid >> 5, lane = tid & 31;
    int warp_m = wid & 3, warp_n = wid >> 2;
    int rbase = bm * 128 + warp_m * 32 + (lane >> 2);
    int cbase = bn * 128 + warp_n * 64 + (lane & 3) * 2;
#pragma unroll
    for (int mt = 0; mt < 2; mt++) {
#pragma unroll
        for (int h = 0; h < 2; h++) {
            int r = rbase + mt * 16 + h * 8;
            float sr = srow ? srow[r & 15] : 1.f;
            OutT* crow = C + (size_t)r * DIMC;
#pragma unroll
            for (int nt = 0; nt < 8; nt++) {
                int c = cbase + nt * 8;
                float ox = (acc[mt][nt][h * 2 + 0] + sr * biascol[c]) * alpha;
                float oy = (acc[mt][nt][h * 2 + 1] + sr * biascol[c + 1]) * alpha;
                if constexpr (sizeof(OutT) == 2) {
                    *(__half2*)(crow + c) = __floats2half2_rn(ox, oy);
                } else {
                    *(float2*)(crow + c) = make_float2(ox, oy);
                }
            }
        }
    }
}

template <typename OutT>
__global__ __launch_bounds__(256, 2) void tgemm_kernel(
    const __half* __restrict__ A, const __half* __restrict__ Bt,
    OutT* __restrict__ C,
    const float* __restrict__ biascol, const float* __restrict__ srow, float alpha) {
    extern __shared__ __align__(16) char smem[];
    float acc[2][8][4];
    gemm_mainloop64(A + (size_t)blockIdx.y * 128 * DIMC,
                    Bt + (size_t)blockIdx.x * 128 * DIMC, smem_u32(smem), acc);
    gemm_epilogue<OutT>(C, blockIdx.y, blockIdx.x, acc, biascol, srow, alpha);
}

// fused KP/VP GEMM: blockIdx.y selects K half vs V half
__global__ __launch_bounds__(256, 2) void kvgemm_kernel(
    const float* __restrict__ b_qkv) {
    extern __shared__ __align__(16) char smem[];
    int by = blockIdx.y;
    int isV = (by >= MP / 128);
    int bm = isV ? by - MP / 128 : by;
    const __half* A  = isV ? g_XV : g_XK;
    const __half* Bt = g_WT + (size_t)(1 + isV) * DIMC * DIMC;
    __half* C        = isV ? g_VP16 : g_KP16;
    float acc[2][8][4];
    gemm_mainloop64(A + (size_t)bm * 128 * DIMC,
                    Bt + (size_t)blockIdx.x * 128 * DIMC, smem_u32(smem), acc);
    gemm_epilogue<__half>(C, bm, blockIdx.x, acc,
                          b_qkv + (1 + isV) * DIMC, isV ? g_sv : g_sk, 1.f);
}

// ============ fused Q-GEMM + attention (BK=32 mainloop, UNCHANGED) =========
#define QS_BYTES 67584                 // 128*132*4
#define QA_SMEM  (QS_BYTES + 2 * 8192)

__global__ __launch_bounds__(256, 2) void qattn_kernel(
    const float* __restrict__ b_qkv, const float* __restrict__ btab) {
    extern __shared__ __align__(16) char smem[];
    uint32_t sb = smem_u32(smem);
    float*  qs  = (float*)smem;
    __half* kps = (__half*)(smem + QS_BYTES);
    __half* vps = (__half*)(smem + QS_BYTES + 8192);
    uint32_t kv_s = sb + QS_BYTES;

    int tid = threadIdx.x;
    int wid = tid >> 5, lane = tid & 31;
    int bn = blockIdx.x, bm = blockIdx.y;

    // prologue cp.async group: this CTA's KP/VP slices (drained by first wait1)
#pragma unroll
    for (int i = 0; i < 2; i++) {
        int c = tid + i * 256;
        int row = c >> 4, off = c & 15;
        size_t gofs = (size_t)(bm * 32 + row) * DIMC + bn * 128 + off * 8;
        cp16(kv_s + row * 256 + off * 16, g_KP16 + gofs);
        cp16(kv_s + 8192 + row * 256 + off * 16, g_VP16 + gofs);
    }
    cp_commit();

    float acc[2][8][4];
    gemm_mainloop(g_x16 + (size_t)bm * 128 * DIMC,
                  g_WT + (size_t)bn * 128 * DIMC, sb, acc);
    // mainloop ends with __syncthreads(): stages dead, safe to overwrite with q_s

    const float scale = 0.17677669529663687f;
    {
        int warp_m = wid & 3, warp_n = wid >> 2;
        int rl = warp_m * 32 + (lane >> 2);
        int clb = warp_n * 64 + (lane & 3) * 2;
#pragma unroll
        for (int mt = 0; mt < 2; mt++)
#pragma unroll
            for (int h = 0; h < 2; h++) {
                int r = rl + mt * 16 + h * 8;
#pragma unroll
                for (int nt = 0; nt < 8; nt++) {
                    int c = clb + nt * 8;
                    float bx = b_qkv[bn * 128 + c];
                    float by = b_qkv[bn * 128 + c + 1];
                    qs[(c) * 132 + r]     = (acc[mt][nt][h * 2 + 0] + bx) * scale;
                    qs[(c + 1) * 132 + r] = (acc[mt][nt][h * 2 + 1] + by) * scale;
                }
            }
    }
    __syncthreads();

    // attention: 512 tasks (wb, hl, n) over 256 threads
#pragma unroll
    for (int it = 0; it < 2; it++) {
        int task = tid + it * 256;
        int wb = task >> 8, rem = task & 255;
        int hl = rem >> 6, n = rem & 63;
        int row = wb * 64 + n;
        int h = bn * 4 + hl;

        float q[HD];
#pragma unroll
        for (int d = 0; d < HD; d++) q[d] = qs[(hl * 32 + d) * 132 + row];

        int yn = n >> 3, xn = n & 7;
        float logit[PP];
#pragma unroll
        for (int p = 0; p < PP; p++) {
            const __half2* kr = (const __half2*)(kps + (wb * 16 + p) * 128 + hl * 32);
            float s = 0.f;
#pragma unroll
            for (int d2 = 0; d2 < 16; d2++) {
                float2 f = __half22float2(kr[d2]);
                s += q[2 * d2] * f.x + q[2 * d2 + 1] * f.y;
            }
            int yp = p >> 3, xp = p & 7;
            int idx = (yn - yp + 7) * 15 + (xn - xp + 7);
            logit[p] = s + btab[idx * NH + h];
        }
        float m = logit[0];
#pragma unroll
        for (int p = 1; p < PP; p++) m = fmaxf(m, logit[p]);
        float sum = 0.f;
#pragma unroll
        for (int p = 0; p < PP; p++) {
            float e = __expf(logit[p] - m);
            logit[p] = e;
            sum += e;
        }
        float inv = 1.f / sum;
        float o[HD];
#pragma unroll
        for (int d = 0; d < HD; d++) o[d] = 0.f;
#pragma unroll
        for (int p = 0; p < PP; p++) {
            float w = logit[p] * inv;
            const __half2* vr = (const __half2*)(vps + (wb * 16 + p) * 128 + hl * 32);
#pragma unroll
            for (int d2 = 0; d2 < 16; d2++) {
                float2 f = __half22float2(vr[d2]);
                o[2 * d2] += w * f.x;
                o[2 * d2 + 1] += w * f.y;
            }
        }
        __half2* orow = (__half2*)(g_O16 + ((size_t)(bm * 128 + row)) * DIMC + bn * 128 + hl * 32);
#pragma unroll
        for (int d2 = 0; d2 < 16; d2++)
            orow[d2] = __floats2half2_rn(o[2 * d2], o[2 * d2 + 1]);
    }
}

// ---------------------------------------------------------------------------
extern "C" void kernel_launch(void* const* d_in, const int* in_sizes, int n_in,
                              void* d_out, int out_size) {
    const float* x      = (const float*)d_in[0];
    const float* w_qkv  = (const float*)d_in[1];
    const float* b_qkv  = (const float*)d_in[2];
    const float* w_proj = (const float*)d_in[3];
    const float* b_proj = (const float*)d_in[4];
    const float* w_k    = (const float*)d_in[5];
    const float* w_v    = (const float*)d_in[6];
    const float* btab   = (const float*)d_in[7];
    float* out = (float*)d_out;

    __half *O16, *WT;
    cudaGetSymbolAddress((void**)&O16, g_O16);
    cudaGetSymbolAddress((void**)&WT,  g_WT);

    cudaFuncSetAttribute(tgemm_kernel<float>, cudaFuncAttributeMaxDynamicSharedMemorySize, DYN_SMEM64);
    cudaFuncSetAttribute(kvgemm_kernel, cudaFuncAttributeMaxDynamicSharedMemorySize, DYN_SMEM64);
    cudaFuncSetAttribute(qattn_kernel, cudaFuncAttributeMaxDynamicSharedMemorySize, QA_SMEM);
    cudaFuncSetAttribute(xproj_kernel, cudaFuncAttributeMaxDynamicSharedMemorySize, XP_SMEM);

    transpose_kernel<<<dim3(16, 16, 4), dim3(32, 8)>>>(w_qkv, w_proj);
    rowsum_kernel<<<1, 32>>>(w_k, w_v);
    xproj_kernel<<<B_WIN, 256, XP_SMEM>>>(x, w_k, w_v);

    // KP16 / VP16 in one launch (BK=64 mainloop)
    kvgemm_kernel<<<dim3(4, 2 * MP / 128), 256, DYN_SMEM64>>>(b_qkv);

    // fused Q-GEMM + attention -> O16 (proven BK=32 mainloop)
    qattn_kernel<<<dim3(4, MQ / 128), 256, QA_SMEM>>>(b_qkv, btab);

    // out = O @ w_proj + b_proj   (fp32 out, BK=64 mainloop)
    tgemm_kernel<float><<<dim3(4, MQ / 128), 256, DYN_SMEM64>>>(
        O16, WT + 3 * DIMC * DIMC, out, b_proj, nullptr, 1.f);
}

// round 17
// speedup vs baseline: 1.1203x; 1.0092x over previous
#include <cuda_runtime.h>
#include <cuda_fp16.h>
#include <cstdint>
#include <math.h>

#define B_WIN 2048
#define N_TOK 64
#define DIMC  512
#define NH    16
#define HD    32
#define PP    16
#define MQ    (B_WIN * N_TOK)   // 131072
#define MP    (B_WIN * PP)      // 32768

// ---------------- scratch (allocation-free rule: __device__ globals) --------
__device__ __half g_x16[(size_t)MQ * DIMC];
__device__ __half g_XK [(size_t)MP * DIMC];
__device__ __half g_XV [(size_t)MP * DIMC];
__device__ __half g_KP16[(size_t)MP * DIMC];
__device__ __half g_VP16[(size_t)MP * DIMC];
__device__ __half g_O16[(size_t)MQ * DIMC];
__device__ __half g_WT [4 * DIMC * DIMC];     // transposed weights [N,K] K-major fp16
__device__ float  g_sk[PP];
__device__ float  g_sv[PP];

// ======================= PTX helpers =======================================
__device__ __forceinline__ uint32_t smem_u32(const void* p) {
    uint32_t a;
    asm("{ .reg .u64 t; cvta.to.shared.u64 t, %1; cvt.u32.u64 %0, t; }" : "=r"(a) : "l"(p));
    return a;
}
__device__ __forceinline__ void cp16(uint32_t saddr, const void* g) {
    asm volatile("cp.async.cg.shared.global [%0], [%1], 16;" :: "r"(saddr), "l"(g));
}
__device__ __forceinline__ void cp_commit() { asm volatile("cp.async.commit_group;"); }
__device__ __forceinline__ void cp_wait1()  { asm volatile("cp.async.wait_group 1;"); }
__device__ __forceinline__ void cp_wait0()  { asm volatile("cp.async.wait_group 0;"); }
__device__ __forceinline__ void ldsm_x4(uint32_t* r, uint32_t addr) {
    asm volatile("ldmatrix.sync.aligned.m8n8.x4.shared.b16 {%0,%1,%2,%3}, [%4];"
        : "=r"(r[0]), "=r"(r[1]), "=r"(r[2]), "=r"(r[3]) : "r"(addr));
}
__device__ __forceinline__ void mma16816(float* c, const uint32_t* a, const uint32_t* b) {
    asm volatile("mma.sync.aligned.m16n8k16.row.col.f32.f16.f16.f32 "
        "{%0,%1,%2,%3}, {%4,%5,%6,%7}, {%8,%9}, {%0,%1,%2,%3};"
        : "+f"(c[0]), "+f"(c[1]), "+f"(c[2]), "+f"(c[3])
        : "r"(a[0]), "r"(a[1]), "r"(a[2]), "r"(a[3]), "r"(b[0]), "r"(b[1]));
}

// ------- weight transpose -> fp16 [N,K]  (+ folded w_k/w_v rowsums) --------
__global__ void transpose_kernel(const float* __restrict__ w_qkv,
                                 const float* __restrict__ w_proj,
                                 const float* __restrict__ w_k,
                                 const float* __restrict__ w_v) {
    __shared__ float t[32][33];
    int m = blockIdx.z;
    const float* src = (m < 3) ? w_qkv : w_proj;
    int ld = (m < 3) ? 3 * DIMC : DIMC;
    int coloff = (m < 3) ? m * DIMC : 0;
    int bx = blockIdx.x * 32, by = blockIdx.y * 32;
    int tx = threadIdx.x, ty = threadIdx.y;
#pragma unroll
    for (int i = 0; i < 32; i += 8)
        t[ty + i][tx] = src[(size_t)(by + ty + i) * ld + coloff + bx + tx];
    __syncthreads();
    __half* dst = g_WT + (size_t)m * DIMC * DIMC;
#pragma unroll
    for (int i = 0; i < 32; i += 8)
        dst[(size_t)(bx + ty + i) * DIMC + by + tx] = __float2half_rn(t[tx][ty + i]);

    // folded rowsum (one block only)
    if (m == 0 && blockIdx.x == 0 && blockIdx.y == 0 && ty == 0 && tx < PP) {
        float s1 = 0.f, s2 = 0.f;
        for (int n = 0; n < N_TOK; n++) {
            s1 += w_k[tx * N_TOK + n];
            s2 += w_v[tx * N_TOK + n];
        }
        g_sk[tx] = s1;
        g_sv[tx] = s2;
    }
}

// ====== fused xproj: reads x fp32 once, emits x16 + XK + XV (all fp16) =====
#define XP_STAGE_F (16 * DIMC)
#define XP_SMEM    (2 * XP_STAGE_F * 4 + 64 * PP * 8)

__global__ __launch_bounds__(256, 2) void xproj_kernel(
    const float* __restrict__ x,
    const float* __restrict__ w_k, const float* __restrict__ w_v) {
    extern __shared__ __align__(16) char xsm[];
    float*  xs  = (float*)xsm;
    float2* swp = (float2*)(xsm + 2 * XP_STAGE_F * 4);
    uint32_t sbase = smem_u32(xsm);

    int b = blockIdx.x;
    int t = threadIdx.x;
    const float* xg = x + (size_t)b * N_TOK * DIMC;

    for (int i = t; i < N_TOK * PP; i += 256) {
        int p = i & 15, n = i >> 4;
        swp[n * PP + p] = make_float2(w_k[p * N_TOK + n], w_v[p * N_TOK + n]);
    }

    auto load_stage = [&](int s) {
        uint32_t dst = sbase + (s & 1) * (XP_STAGE_F * 4);
        const float* src = xg + (size_t)s * XP_STAGE_F;
#pragma unroll
        for (int i = 0; i < 8; i++)
            cp16(dst + t * 16 + i * 4096, src + t * 4 + i * 1024);
    };

    float2 ak[PP], av[PP];
#pragma unroll
    for (int p = 0; p < PP; p++) { ak[p] = make_float2(0.f, 0.f); av[p] = make_float2(0.f, 0.f); }

    load_stage(0); cp_commit();

    for (int s = 0; s < 4; s++) {
        if (s < 3) { load_stage(s + 1); cp_commit(); cp_wait1(); }
        else cp_wait0();
        __syncthreads();
        const float* buf = xs + (s & 1) * XP_STAGE_F;
#pragma unroll 4
        for (int nl = 0; nl < 16; nl++) {
            int n = s * 16 + nl;
            float2 xv = *(const float2*)(buf + nl * DIMC + 2 * t);
            *(__half2*)(g_x16 + ((size_t)b * N_TOK + n) * DIMC + 2 * t) =
                __floats2half2_rn(xv.x, xv.y);
            const float2* wrow = swp + n * PP;
#pragma unroll
            for (int p = 0; p < PP; p++) {
                float2 w = wrow[p];
                ak[p].x += w.x * xv.x; ak[p].y += w.x * xv.y;
                av[p].x += w.y * xv.x; av[p].y += w.y * xv.y;
            }
        }
        __syncthreads();
    }

#pragma unroll
    for (int p = 0; p < PP; p++) {
        size_t row = (size_t)b * PP + p;
        *(__half2*)(g_XK + row * DIMC + 2 * t) = __floats2half2_rn(ak[p].x, ak[p].y);
        *(__half2*)(g_XV + row * DIMC + 2 * t) = __floats2half2_rn(av[p].x, av[p].y);
    }
}

// =========== BK=64 mainloop: lockstep two-barrier pattern (proven) =========
// Pitch 144 B (72 halfs: 64 data + 8 pad); conflict-free ldsm + cp.async.
#define STAGE64 36864              // (128 + 128) rows * 144 B
#define DYN_SMEM64 (3 * STAGE64)   // 110592 -> 2 CTAs/SM

__device__ __forceinline__ void gemm_mainloop64(
    const __half* __restrict__ Ag, const __half* __restrict__ Bg,
    uint32_t sb, float acc[2][8][4]) {
    int tid = threadIdx.x;
    int wid = tid >> 5, lane = tid & 31;

    int grow = tid >> 3, gcol = tid & 7;
    auto load_stage = [&](int kc, int st) {
        uint32_t a0 = sb + st * STAGE64;
        uint32_t b0 = a0 + 18432;
        const __half* Agk = Ag + kc * 64;
        const __half* Bgk = Bg + kc * 64;
#pragma unroll
        for (int i = 0; i < 4; i++) {
            int row = grow + i * 32;
            cp16(a0 + row * 144 + gcol * 16, Agk + (size_t)row * DIMC + gcol * 8);
            cp16(b0 + row * 144 + gcol * 16, Bgk + (size_t)row * DIMC + gcol * 8);
        }
    };

#pragma unroll
    for (int mt = 0; mt < 2; mt++)
#pragma unroll
        for (int nt = 0; nt < 8; nt++)
#pragma unroll
            for (int e = 0; e < 4; e++) acc[mt][nt][e] = 0.f;

    int warp_m = wid & 3, warp_n = wid >> 2;
    int arow = (lane & 7) + ((lane >> 3) & 1) * 8;
    int achk = lane >> 4;
    int brow = (lane & 7) + ((lane >> 4) & 1) * 8;
    int bchk = (lane >> 3) & 1;

    load_stage(0, 0); cp_commit();
    load_stage(1, 1); cp_commit();

    const int NK = 8;
    for (int kc = 0; kc < NK; kc++) {
        int st = kc % 3;
        cp_wait1();
        __syncthreads();
        if (kc + 2 < NK) load_stage(kc + 2, (kc + 2) % 3);
        cp_commit();

        uint32_t aS = sb + st * STAGE64;
        uint32_t bS = aS + 18432;
#pragma unroll
        for (int ks = 0; ks < 4; ks++) {
            uint32_t af[2][4];
            uint32_t abase = aS + (uint32_t)((warp_m * 32 + arow) * 144 + ks * 32 + achk * 16);
            ldsm_x4(af[0], abase);
            ldsm_x4(af[1], abase + 16 * 144);
            uint32_t bf[8][2];
#pragma unroll
            for (int bt = 0; bt < 4; bt++) {
                uint32_t t4[4];
                ldsm_x4(t4, bS + (uint32_t)((warp_n * 64 + bt * 16 + brow) * 144 + ks * 32 + bchk * 16));
                bf[2 * bt][0] = t4[0]; bf[2 * bt][1] = t4[1];
                bf[2 * bt + 1][0] = t4[2]; bf[2 * bt + 1][1] = t4[3];
            }
#pragma unroll
            for (int mt = 0; mt < 2; mt++)
#pragma unroll
                for (int nt = 0; nt < 8; nt++)
                    mma16816(acc[mt][nt], af[mt], bf[nt]);
        }
        __syncthreads();
    }
}

// =================== plain GEMM kernels (out-proj, KV) =====================
template <typename OutT>
__device__ __forceinline__ void gemm_epilogue(
    OutT* __restrict__ C, int bm, int bn, float acc[2][8][4],
    const float* __restrict__ biascol, const float* __restrict__ srow, float alpha) {
    int tid = threadIdx.x;
    int wid = tid >> 5, lane = tid & 31;
    int warp_m = wid & 3, warp_n = wid >> 2;
    int rbase = bm * 128 + warp_m * 32 + (lane >> 2);
    int cbase = bn * 128 + warp_n * 64 + (lane & 3) * 2;
#pragma unroll
    for (int mt = 0; mt < 2; mt++) {
#pragma unroll
        for (int h = 0; h < 2; h++) {
            int r = rbase + mt * 16 + h * 8;
            float sr = srow ? srow[r & 15] : 1.f;
            OutT* crow = C + (size_t)r * DIMC;
#pragma unroll
            for (int nt = 0; nt < 8; nt++) {
                int c = cbase + nt * 8;
                float ox = (acc[mt][nt][h * 2 + 0] + sr * biascol[c]) * alpha;
                float oy = (acc[mt][nt][h * 2 + 1] + sr * biascol[c + 1]) * alpha;
                if constexpr (sizeof(OutT) == 2) {
                    *(__half2*)(crow + c) = __floats2half2_rn(ox, oy);
                } else {
                    *(float2*)(crow + c) = make_float2(ox, oy);
                }
            }
        }
    }
}

template <typename OutT>
__global__ __launch_bounds__(256, 2) void tgemm_kernel(
    const __half* __restrict__ A, const __half* __restrict__ Bt,
    OutT* __restrict__ C,
    const float* __restrict__ biascol, const float* __restrict__ srow, float alpha) {
    extern __shared__ __align__(16) char smem[];
    float acc[2][8][4];
    gemm_mainloop64(A + (size_t)blockIdx.y * 128 * DIMC,
                    Bt + (size_t)blockIdx.x * 128 * DIMC, smem_u32(smem), acc);
    gemm_epilogue<OutT>(C, blockIdx.y, blockIdx.x, acc, biascol, srow, alpha);
}

// fused KP/VP GEMM: blockIdx.y selects K half vs V half
__global__ __launch_bounds__(256, 2) void kvgemm_kernel(
    const float* __restrict__ b_qkv) {
    extern __shared__ __align__(16) char smem[];
    int by = blockIdx.y;
    int isV = (by >= MP / 128);
    int bm = isV ? by - MP / 128 : by;
    const __half* A  = isV ? g_XV : g_XK;
    const __half* Bt = g_WT + (size_t)(1 + isV) * DIMC * DIMC;
    __half* C        = isV ? g_VP16 : g_KP16;
    float acc[2][8][4];
    gemm_mainloop64(A + (size_t)bm * 128 * DIMC,
                    Bt + (size_t)blockIdx.x * 128 * DIMC, smem_u32(smem), acc);
    gemm_epilogue<__half>(C, bm, blockIdx.x, acc,
                          b_qkv + (1 + isV) * DIMC, isV ? g_sv : g_sk, 1.f);
}

// ============ fused Q-GEMM + attention (now BK=64 mainloop) ================
// KV tiles loaded AFTER the mainloop into the then-dead pipeline region:
// qs fp32 [128 cols][132 rows] at [0, 67584), KV fp16 at [67584, 83968) —
// both inside the 110592-byte pipeline footprint, so smem = DYN_SMEM64 and
// occupancy stays 2 CTAs/SM. KV cp.async latency hides behind the qs writes.
#define QS_BYTES 67584                 // 128*132*4
#define QA_SMEM  DYN_SMEM64

__global__ __launch_bounds__(256, 2) void qattn_kernel(
    const float* __restrict__ b_qkv, const float* __restrict__ btab) {
    extern __shared__ __align__(16) char smem[];
    uint32_t sb = smem_u32(smem);
    float*  qs  = (float*)smem;
    __half* kps = (__half*)(smem + QS_BYTES);
    __half* vps = (__half*)(smem + QS_BYTES + 8192);
    uint32_t kv_s = sb + QS_BYTES;

    int tid = threadIdx.x;
    int wid = tid >> 5, lane = tid & 31;
    int bn = blockIdx.x, bm = blockIdx.y;

    float acc[2][8][4];
    gemm_mainloop64(g_x16 + (size_t)bm * 128 * DIMC,
                    g_WT + (size_t)bn * 128 * DIMC, sb, acc);
    // mainloop ends with __syncthreads(): pipeline stages dead from here.

    // KV load into dead stage space (latency overlapped with qs writes below)
#pragma unroll
    for (int i = 0; i < 2; i++) {
        int c = tid + i * 256;
        int row = c >> 4, off = c & 15;
        size_t gofs = (size_t)(bm * 32 + row) * DIMC + bn * 128 + off * 8;
        cp16(kv_s + row * 256 + off * 16, g_KP16 + gofs);
        cp16(kv_s + 8192 + row * 256 + off * 16, g_VP16 + gofs);
    }
    cp_commit();

    const float scale = 0.17677669529663687f;
    {
        int warp_m = wid & 3, warp_n = wid >> 2;
        int rl = warp_m * 32 + (lane >> 2);
        int clb = warp_n * 64 + (lane & 3) * 2;
#pragma unroll
        for (int mt = 0; mt < 2; mt++)
#pragma unroll
            for (int h = 0; h < 2; h++) {
                int r = rl + mt * 16 + h * 8;
#pragma unroll
                for (int nt = 0; nt < 8; nt++) {
                    int c = clb + nt * 8;
                    float bx = b_qkv[bn * 128 + c];
                    float by = b_qkv[bn * 128 + c + 1];
                    qs[(c) * 132 + r]     = (acc[mt][nt][h * 2 + 0] + bx) * scale;
                    qs[(c + 1) * 132 + r] = (acc[mt][nt][h * 2 + 1] + by) * scale;
                }
            }
    }
    cp_wait0();
    __syncthreads();

    // attention: 512 tasks (wb, hl, n) over 256 threads
#pragma unroll
    for (int it = 0; it < 2; it++) {
        int task = tid + it * 256;
        int wb = task >> 8, rem = task & 255;
        int hl = rem >> 6, n = rem & 63;
        int row = wb * 64 + n;
        int h = bn * 4 + hl;

        float q[HD];
#pragma unroll
        for (int d = 0; d < HD; d++) q[d] = qs[(hl * 32 + d) * 132 + row];

        int yn = n >> 3, xn = n & 7;
        float logit[PP];
#pragma unroll
        for (int p = 0; p < PP; p++) {
            const __half2* kr = (const __half2*)(kps + (wb * 16 + p) * 128 + hl * 32);
            float s = 0.f;
#pragma unroll
            for (int d2 = 0; d2 < 16; d2++) {
                float2 f = __half22float2(kr[d2]);
                s += q[2 * d2] * f.x + q[2 * d2 + 1] * f.y;
            }
            int yp = p >> 3, xp = p & 7;
            int idx = (yn - yp + 7) * 15 + (xn - xp + 7);
            logit[p] = s + btab[idx * NH + h];
        }
        float m = logit[0];
#pragma unroll
        for (int p = 1; p < PP; p++) m = fmaxf(m, logit[p]);
        float sum = 0.f;
#pragma unroll
        for (int p = 0; p < PP; p++) {
            float e = __expf(logit[p] - m);
            logit[p] = e;
            sum += e;
        }
        float inv = 1.f / sum;
        float o[HD];
#pragma unroll
        for (int d = 0; d < HD; d++) o[d] = 0.f;
#pragma unroll
        for (int p = 0; p < PP; p++) {
            float w = logit[p] * inv;
            const __half2* vr = (const __half2*)(vps + (wb * 16 + p) * 128 + hl * 32);
#pragma unroll
            for (int d2 = 0; d2 < 16; d2++) {
                float2 f = __half22float2(vr[d2]);
                o[2 * d2] += w * f.x;
                o[2 * d2 + 1] += w * f.y;
            }
        }
        __half2* orow = (__half2*)(g_O16 + ((size_t)(bm * 128 + row)) * DIMC + bn * 128 + hl * 32);
#pragma unroll
        for (int d2 = 0; d2 < 16; d2++)
            orow[d2] = __floats2half2_rn(o[2 * d2], o[2 * d2 + 1]);
    }
}

// ---------------------------------------------------------------------------
extern "C" void kernel_launch(void* const* d_in, const int* in_sizes, int n_in,
                              void* d_out, int out_size) {
    const float* x      = (const float*)d_in[0];
    const float* w_qkv  = (const float*)d_in[1];
    const float* b_qkv  = (const float*)d_in[2];
    const float* w_proj = (const float*)d_in[3];
    const float* b_proj = (const float*)d_in[4];
    const float* w_k    = (const float*)d_in[5];
    const float* w_v    = (const float*)d_in[6];
    const float* btab   = (const float*)d_in[7];
    float* out = (float*)d_out;

    __half *O16, *WT;
    cudaGetSymbolAddress((void**)&O16, g_O16);
    cudaGetSymbolAddress((void**)&WT,  g_WT);

    cudaFuncSetAttribute(tgemm_kernel<float>, cudaFuncAttributeMaxDynamicSharedMemorySize, DYN_SMEM64);
    cudaFuncSetAttribute(kvgemm_kernel, cudaFuncAttributeMaxDynamicSharedMemorySize, DYN_SMEM64);
    cudaFuncSetAttribute(qattn_kernel, cudaFuncAttributeMaxDynamicSharedMemorySize, QA_SMEM);
    cudaFuncSetAttribute(xproj_kernel, cudaFuncAttributeMaxDynamicSharedMemorySize, XP_SMEM);

    transpose_kernel<<<dim3(16, 16, 4), dim3(32, 8)>>>(w_qkv, w_proj, w_k, w_v);
    xproj_kernel<<<B_WIN, 256, XP_SMEM>>>(x, w_k, w_v);

    // KP16 / VP16 in one launch (BK=64 mainloop)
    kvgemm_kernel<<<dim3(4, 2 * MP / 128), 256, DYN_SMEM64>>>(b_qkv);

    // fused Q-GEMM + attention -> O16 (BK=64 mainloop, deferred KV load)
    qattn_kernel<<<dim3(4, MQ / 128), 256, QA_SMEM>>>(b_qkv, btab);

    // out = O @ w_proj + b_proj   (fp32 out, BK=64 mainloop)
    tgemm_kernel<float><<<dim3(4, MQ / 128), 256, DYN_SMEM64>>>(
        O16, WT + 3 * DIMC * DIMC, out, b_proj, nullptr, 1.f);
}